// round 6
// baseline (speedup 1.0000x reference)
#include <cuda_runtime.h>
#include <cuda_fp16.h>
#include <cstdint>
#include <cstddef>

// Problem constants
#define T_TOK 2048
#define D_DIM 512
#define H_DIM 2048
#define N_EXP 8
#define BM 128
#define BN 256
#define BK 32                  // K elements per chunk (2 k16 steps)
#define PAD_ROWS 3072
#define MAX_TILES 24

// fp16 smem layout (uint32 words; each word = 2 halves = k-pair or n-pair)
#define AS_STRIDE 20           // 16 words (32 halves) + 4 pad; conflict-free
#define BS_STRIDE 264          // 256 words + 8 pad
#define A_STAGE_WORDS (BM * AS_STRIDE)        // 2560
#define B_STAGE_WORDS (16 * BS_STRIDE)        // 16 kp-rows -> 4224
#define STAGE_WORDS (A_STAGE_WORDS + B_STAGE_WORDS)   // 6784
#define STAGES 4
#define SMEM_BYTES (STAGES * STAGE_WORDS * 4)          // 108544

// GEMM2 split-K over 64 chunks: 22/21/21
#define G2_CHUNKS 64
#define NSPLIT 3

// fp16 conversion sizes (in uint32 words)
#define NW_X  (T_TOK * D_DIM / 2)              // 524288
#define NW_PE (D_DIM * H_DIM / 2)              // 524288 per expert (same W1/W2)
#define NW_W  (N_EXP * NW_PE)                  // 4194304
#define NW_TOTAL (NW_X + 2 * NW_W)

// Scratch (device globals: allocation-free rule)
__device__ int      g_perm[PAD_ROWS];
__device__ int      g_tile_expert[MAX_TILES + 8];
__device__ uint32_t g_xh[NW_X];                      // x fp16 row-major
__device__ uint32_t g_w1h[NW_W];                     // W1 fp16 kp-interleaved [e][kp][n]
__device__ uint32_t g_w2h[NW_W];                     // W2 fp16 kp-interleaved
__device__ uint32_t g_hh[(size_t)PAD_ROWS * (H_DIM / 2)];  // h fp16 row-major
__device__ float    g_ffn[NSPLIT][(size_t)T_TOK * D_DIM];

__device__ __forceinline__ void cp16(uint32_t dst, const void* src, bool pred) {
    int sz = pred ? 16 : 0;
    asm volatile("cp.async.cg.shared.global [%0], [%1], 16, %2;\n"
                 :: "r"(dst), "l"(src), "r"(sz));
}
__device__ __forceinline__ void cp_commit() { asm volatile("cp.async.commit_group;\n"); }
template <int N> __device__ __forceinline__ void cp_wait() {
    asm volatile("cp.async.wait_group %0;\n" :: "n"(N));
}

// fp16 m16n8k16, fp32 accum
__device__ __forceinline__ void mma16(float* c,
                                      uint32_t a0, uint32_t a1, uint32_t a2, uint32_t a3,
                                      uint32_t b0, uint32_t b1) {
    asm volatile(
        "mma.sync.aligned.m16n8k16.row.col.f32.f16.f16.f32 "
        "{%0,%1,%2,%3}, {%4,%5,%6,%7}, {%8,%9}, {%0,%1,%2,%3};\n"
        : "+f"(c[0]), "+f"(c[1]), "+f"(c[2]), "+f"(c[3])
        : "r"(a0), "r"(a1), "r"(a2), "r"(a3), "r"(b0), "r"(b1));
}

__device__ __forceinline__ uint32_t pack2(float a, float b) {
    __half2 h = __floats2half2_rn(a, b);
    return *reinterpret_cast<uint32_t*>(&h);
}

// ---------------------------------------------------------------------------
// Setup: bins -> histogram -> padded grouped permutation + tile expert table
// ---------------------------------------------------------------------------
__global__ void setup_kernel(const int* __restrict__ orig, const int* __restrict__ hmap) {
    __shared__ int cnt[N_EXP];
    __shared__ int padoff[N_EXP];
    __shared__ int scat[N_EXP];
    int tid = threadIdx.x;

    if (tid < N_EXP) cnt[tid] = 0;
    __syncthreads();

    for (int t = tid; t < T_TOK; t += 256) {
        int b = hmap[orig[t]];
        atomicAdd(&cnt[b], 1);
    }
    for (int i = tid; i < PAD_ROWS; i += 256) g_perm[i] = -1;
    if (tid < MAX_TILES + 8) g_tile_expert[tid] = -1;
    __syncthreads();

    if (tid == 0) {
        int tile = 0;
        for (int e = 0; e < N_EXP; e++) {
            padoff[e] = tile * BM;
            scat[e] = 0;
            int nt = (cnt[e] + BM - 1) / BM;
            for (int i = 0; i < nt; i++) g_tile_expert[tile++] = e;
        }
    }
    __syncthreads();

    for (int t = tid; t < T_TOK; t += 256) {
        int b = hmap[orig[t]];
        int r = atomicAdd(&scat[b], 1);
        g_perm[padoff[b] + r] = t;
    }
}

// ---------------------------------------------------------------------------
// Convert fp32 inputs to fp16:
//   x  -> g_xh  row-major k-pairs (word = (x[r][2c], x[r][2c+1]))
//   W1 -> g_w1h kp-interleaved (word(e,kp,n) = (W1[e][2kp][n], W1[e][2kp+1][n]))
//   W2 -> g_w2h kp-interleaved
// ---------------------------------------------------------------------------
__global__ void convert_kernel(const float* __restrict__ x,
                               const float* __restrict__ W1,
                               const float* __restrict__ W2) {
    int id = blockIdx.x * 256 + threadIdx.x;
    if (id < NW_X) {
        const float2 v = *(const float2*)(x + (size_t)id * 2);
        g_xh[id] = pack2(v.x, v.y);
        return;
    }
    int j = id - NW_X;
    if (j < NW_W) {
        int e = j >> 19;                 // NW_PE = 2^19
        int kp = (j >> 11) & 255;        // H_DIM=2048 words/row -> n bits 11
        int n = j & 2047;
        const float* base = W1 + (size_t)e * D_DIM * H_DIM + (size_t)(2 * kp) * H_DIM + n;
        g_w1h[j] = pack2(base[0], base[H_DIM]);
        return;
    }
    j -= NW_W;
    if (j < NW_W) {
        int e = j >> 19;
        int kp = (j >> 9) & 1023;        // D_DIM=512 words/row -> n bits 9
        int n = j & 511;
        const float* base = W2 + (size_t)e * H_DIM * D_DIM + (size_t)(2 * kp) * D_DIM + n;
        g_w2h[j] = pack2(base[0], base[D_DIM]);
    }
}

// ---------------------------------------------------------------------------
// Warp compute on one stage: warp tile 64x64, 2 k16 steps
// ---------------------------------------------------------------------------
__device__ __forceinline__ void compute_stage(const uint32_t* As, const uint32_t* Bs,
                                              float acc[4][8][4],
                                              int wm, int wn, int gid, int tig) {
#pragma unroll
    for (int s = 0; s < 2; ++s) {
        int k0 = s * 8;   // word offset within chunk (8 words = 16 halves per step)
        uint32_t af[4][4], bf[8][2];
#pragma unroll
        for (int mi = 0; mi < 4; ++mi) {
            int r0 = wm * 64 + mi * 16 + gid;
            af[mi][0] = As[r0 * AS_STRIDE + k0 + tig];
            af[mi][1] = As[(r0 + 8) * AS_STRIDE + k0 + tig];
            af[mi][2] = As[r0 * AS_STRIDE + k0 + tig + 4];
            af[mi][3] = As[(r0 + 8) * AS_STRIDE + k0 + tig + 4];
        }
#pragma unroll
        for (int ni = 0; ni < 8; ++ni) {
            int cb = wn * 64 + ni * 8 + gid;
            bf[ni][0] = Bs[(k0 + tig) * BS_STRIDE + cb];
            bf[ni][1] = Bs[(k0 + tig + 4) * BS_STRIDE + cb];
        }
#pragma unroll
        for (int mi = 0; mi < 4; ++mi)
#pragma unroll
            for (int ni = 0; ni < 8; ++ni)
                mma16(acc[mi][ni], af[mi][0], af[mi][1], af[mi][2], af[mi][3],
                      bf[ni][0], bf[ni][1]);
    }
}

// ---------------------------------------------------------------------------
// Unified GEMM (fp16 mma.sync m16n8k16, 128x256 CTA tile, 4-stage cp.async)
//   G1: h = relu(x[perm] @ W1[e] + b1[e]) -> g_hh (fp16)   grid (tiles, H/256)
//   G2: g_ffn[z] = h @ W2[e][ksplit] (+b2)                 grid (tiles, D/256, 3)
// ---------------------------------------------------------------------------
template <bool G1>
__global__ __launch_bounds__(256, 1) void gemm_kernel(const float* __restrict__ bias) {
    int te = g_tile_expert[blockIdx.x];
    if (te < 0) return;

    extern __shared__ uint32_t smx[];
    __shared__ int toks[BM];

    const int tid = threadIdx.x;
    if (tid < BM) toks[tid] = g_perm[blockIdx.x * BM + tid];
    __syncthreads();

    const int ldnw = G1 ? H_DIM : D_DIM;          // B row length in words (= elements)
    const int split = G1 ? 0 : blockIdx.z;
    const int nbase = blockIdx.y * BN;
    const int lane = tid & 31, wid = tid >> 5;
    const int wm = wid & 1, wn = wid >> 1;
    const int gid = lane >> 2, tig = lane & 3;

    // chunk range
    int cb0, ncb;
    if (G1) { cb0 = 0; ncb = D_DIM / BK; }                 // 16
    else {
        int base = (G2_CHUNKS / NSPLIT);                    // 21
        int extra = G2_CHUNKS - base * NSPLIT;              // 1
        cb0 = split * base + (split < extra ? split : extra);
        ncb = base + (split < extra ? 1 : 0);               // 22/21/21
    }

    const uint32_t* Wh = (G1 ? g_w1h : g_w2h) + (size_t)te * NW_PE;

    uint32_t sbase = (uint32_t)__cvta_generic_to_shared(smx);

    // A loads: 512 cp16/chunk -> 2/thread; id = tid + 256j: r = id/4, c4 = (id%4)*4 words
    const int a_r = tid >> 2, a_c4 = (tid & 3) * 4;
    const uint32_t* a_src[2]; bool a_val[2];
#pragma unroll
    for (int j = 0; j < 2; ++j) {
        int r = a_r + 64 * j;
        if (G1) {
            int tk = toks[r];
            a_val[j] = (tk >= 0);
            a_src[j] = g_xh + (size_t)(tk >= 0 ? tk : 0) * (D_DIM / 2) + a_c4;
        } else {
            a_val[j] = true;
            a_src[j] = g_hh + ((size_t)blockIdx.x * BM + r) * (H_DIM / 2) + a_c4;
        }
    }
    // B loads: 1024 cp16/chunk -> 4/thread; id = tid + 256j: kp = id/64, n4 = (id%64)*4
    const int b_kp = tid >> 6, b_n4 = (tid & 63) * 4;

    float acc[4][8][4];
#pragma unroll
    for (int i = 0; i < 4; i++)
#pragma unroll
        for (int j = 0; j < 8; j++)
#pragma unroll
            for (int k = 0; k < 4; k++) acc[i][j][k] = 0.f;

    auto issue = [&](int c) {   // c = local chunk index
        int kb = cb0 + c;
        uint32_t st = sbase + (uint32_t)(c % STAGES) * STAGE_WORDS * 4;
#pragma unroll
        for (int j = 0; j < 2; ++j)
            cp16(st + ((a_r + 64 * j) * AS_STRIDE + a_c4) * 4,
                 a_src[j] + kb * (BK / 2), a_val[j]);
        uint32_t bb = st + A_STAGE_WORDS * 4;
#pragma unroll
        for (int j = 0; j < 4; ++j) {
            int kp = b_kp + 4 * j;                       // 0..15
            cp16(bb + (kp * BS_STRIDE + b_n4) * 4,
                 Wh + (size_t)(kb * 16 + kp) * ldnw + nbase + b_n4, true);
        }
        cp_commit();
    };

    issue(0);
    issue(1);
    issue(2);
    for (int c = 0; c < ncb; ++c) {
        cp_wait<STAGES - 2>();
        __syncthreads();
        if (c + STAGES - 1 < ncb) issue(c + STAGES - 1);
        const uint32_t* As = smx + (c % STAGES) * STAGE_WORDS;
        const uint32_t* Bs = As + A_STAGE_WORDS;
        compute_stage(As, Bs, acc, wm, wn, gid, tig);
        __syncthreads();
    }

    // ---- epilogue ----
    const float* be = bias + (size_t)te * (G1 ? H_DIM : D_DIM);
    if (G1) {
        // write fp16 k-pairs directly (c0, c0+1 contiguous)
        int rowbase = blockIdx.x * BM;
#pragma unroll
        for (int ni = 0; ni < 8; ++ni) {
            int c0 = nbase + wn * 64 + ni * 8 + tig * 2;
            float bb0 = be[c0], bb1 = be[c0 + 1];
#pragma unroll
            for (int mi = 0; mi < 4; ++mi) {
                int r0 = rowbase + wm * 64 + mi * 16 + gid;
                g_hh[(size_t)r0 * (H_DIM / 2) + (c0 >> 1)] =
                    pack2(fmaxf(acc[mi][ni][0] + bb0, 0.f),
                          fmaxf(acc[mi][ni][1] + bb1, 0.f));
                g_hh[(size_t)(r0 + 8) * (H_DIM / 2) + (c0 >> 1)] =
                    pack2(fmaxf(acc[mi][ni][2] + bb0, 0.f),
                          fmaxf(acc[mi][ni][3] + bb1, 0.f));
            }
        }
    } else {
        float* dst = g_ffn[split];
#pragma unroll
        for (int ni = 0; ni < 8; ++ni) {
            int c0 = nbase + wn * 64 + ni * 8 + tig * 2;
            float bb0 = split == 0 ? be[c0] : 0.f;
            float bb1 = split == 0 ? be[c0 + 1] : 0.f;
#pragma unroll
            for (int mi = 0; mi < 4; ++mi) {
                int rl0 = wm * 64 + mi * 16 + gid;
                int tk0 = toks[rl0];
                int tk1 = toks[rl0 + 8];
                if (tk0 >= 0) {
                    float2 v;
                    v.x = acc[mi][ni][0] + bb0;
                    v.y = acc[mi][ni][1] + bb1;
                    *(float2*)(dst + (size_t)tk0 * D_DIM + c0) = v;
                }
                if (tk1 >= 0) {
                    float2 v;
                    v.x = acc[mi][ni][2] + bb0;
                    v.y = acc[mi][ni][3] + bb1;
                    *(float2*)(dst + (size_t)tk1 * D_DIM + c0) = v;
                }
            }
        }
    }
}

// ---------------------------------------------------------------------------
// Residual + LayerNorm (sums the three split-K partials)
// ---------------------------------------------------------------------------
__global__ void ln_kernel(const float* __restrict__ x,
                          const float* __restrict__ gamma,
                          const float* __restrict__ beta,
                          float* __restrict__ out) {
    int t = blockIdx.x;
    int tid = threadIdx.x;  // 128
    size_t off = (size_t)t * D_DIM + tid * 4;

    float4 xv = *(const float4*)(x + off);
    float4 f0 = *(const float4*)(g_ffn[0] + off);
    float4 f1 = *(const float4*)(g_ffn[1] + off);
    float4 f2 = *(const float4*)(g_ffn[2] + off);
    float4 z;
    z.x = xv.x + f0.x + f1.x + f2.x;
    z.y = xv.y + f0.y + f1.y + f2.y;
    z.z = xv.z + f0.z + f1.z + f2.z;
    z.w = xv.w + f0.w + f1.w + f2.w;

    float s = z.x + z.y + z.z + z.w;
    float ss = z.x * z.x + z.y * z.y + z.z * z.z + z.w * z.w;
#pragma unroll
    for (int o = 16; o > 0; o >>= 1) {
        s += __shfl_xor_sync(0xffffffffu, s, o);
        ss += __shfl_xor_sync(0xffffffffu, ss, o);
    }
    __shared__ float sm[8];
    int w = tid >> 5;
    if ((tid & 31) == 0) { sm[w] = s; sm[4 + w] = ss; }
    __syncthreads();
    s = sm[0] + sm[1] + sm[2] + sm[3];
    ss = sm[4] + sm[5] + sm[6] + sm[7];

    float mean = s * (1.f / 512.f);
    float var = ss * (1.f / 512.f) - mean * mean;
    float rstd = rsqrtf(var + 1e-5f);

    float4 gv = *(const float4*)(gamma + tid * 4);
    float4 bv = *(const float4*)(beta + tid * 4);
    float4 o4;
    o4.x = (z.x - mean) * rstd * gv.x + bv.x;
    o4.y = (z.y - mean) * rstd * gv.y + bv.y;
    o4.z = (z.z - mean) * rstd * gv.z + bv.z;
    o4.w = (z.w - mean) * rstd * gv.w + bv.w;
    *(float4*)(out + off) = o4;
}

// ---------------------------------------------------------------------------
extern "C" void kernel_launch(void* const* d_in, const int* in_sizes, int n_in,
                              void* d_out, int out_size) {
    const float* x     = (const float*)d_in[0];
    const float* W1    = (const float*)d_in[1];
    const float* b1    = (const float*)d_in[2];
    const float* W2    = (const float*)d_in[3];
    const float* b2    = (const float*)d_in[4];
    const float* gamma = (const float*)d_in[5];
    const float* beta  = (const float*)d_in[6];
    const int*   orig  = (const int*)d_in[7];
    const int*   hmap  = (const int*)d_in[8];
    float* out = (float*)d_out;

    cudaFuncSetAttribute(gemm_kernel<true>, cudaFuncAttributeMaxDynamicSharedMemorySize, SMEM_BYTES);
    cudaFuncSetAttribute(gemm_kernel<false>, cudaFuncAttributeMaxDynamicSharedMemorySize, SMEM_BYTES);

    setup_kernel<<<1, 256>>>(orig, hmap);
    convert_kernel<<<(NW_TOTAL + 255) / 256, 256>>>(x, W1, W2);
    gemm_kernel<true><<<dim3(MAX_TILES, H_DIM / BN), 256, SMEM_BYTES>>>(b1);
    gemm_kernel<false><<<dim3(MAX_TILES, D_DIM / BN, NSPLIT), 256, SMEM_BYTES>>>(b2);
    ln_kernel<<<T_TOK, 128>>>(x, gamma, beta, out);
}